// round 2
// baseline (speedup 1.0000x reference)
#include <cuda_runtime.h>
#include <cstdint>

#define TOK 16384
#define DID 1024
#define HID 4096
#define NE  8

// ---------------- scratch (__device__ globals: allowed alloc workaround) ----
__device__ int   g_count[NE];
__device__ int   g_off[NE];
__device__ __align__(16) int   g_list[NE][TOK];
__device__ __align__(16) float g_wlist[NE][TOK];
// 2*TOK rows of H floats = 32768 * 4096 * 4B = 512 MB
__device__ __align__(256) float g_hidden[(size_t)2 * TOK * HID];

// ---------------- gate: logits -> top2 -> softmax -> expert lists ----------
__global__ void gate_kernel(const float* __restrict__ x,
                            const float* __restrict__ gw,
                            const float* __restrict__ gb) {
    int warp = (blockIdx.x * blockDim.x + threadIdx.x) >> 5;
    int lane = threadIdx.x & 31;
    if (warp >= TOK) return;
    const float* xr = x + (size_t)warp * DID;
    float p[NE];
#pragma unroll
    for (int e = 0; e < NE; e++) p[e] = 0.f;
#pragma unroll 4
    for (int i = 0; i < DID / 32; i++) {
        int d = i * 32 + lane;
        float xv = xr[d];
        const float4* g4 = reinterpret_cast<const float4*>(gw + (size_t)d * NE);
        float4 g0 = g4[0], g1 = g4[1];
        p[0] += xv * g0.x; p[1] += xv * g0.y; p[2] += xv * g0.z; p[3] += xv * g0.w;
        p[4] += xv * g1.x; p[5] += xv * g1.y; p[6] += xv * g1.z; p[7] += xv * g1.w;
    }
#pragma unroll
    for (int e = 0; e < NE; e++)
#pragma unroll
        for (int o = 16; o > 0; o >>= 1)
            p[e] += __shfl_xor_sync(0xffffffffu, p[e], o);

    if (lane == 0) {
        float l[NE];
#pragma unroll
        for (int e = 0; e < NE; e++) l[e] = p[e] + gb[e];
        int e0 = 0, e1 = -1;
        float b0 = l[0], b1 = -3.0e38f;
#pragma unroll
        for (int e = 1; e < NE; e++) {
            float v = l[e];
            if (v > b0)      { b1 = b0; e1 = e0; b0 = v; e0 = e; }
            else if (v > b1) { b1 = v;  e1 = e; }
        }
        float ex = expf(b1 - b0);         // b1 <= b0, stable
        float inv = 1.f / (1.f + ex);
        float w0 = inv, w1 = ex * inv;
        int t = warp;
        int p0 = atomicAdd(&g_count[e0], 1);
        g_list[e0][p0] = t; g_wlist[e0][p0] = w0;
        int p1 = atomicAdd(&g_count[e1], 1);
        g_list[e1][p1] = t; g_wlist[e1][p1] = w1;
    }
}

__global__ void offs_kernel() {
    int s = 0;
#pragma unroll
    for (int e = 0; e < NE; e++) { g_off[e] = s; s += g_count[e]; }
}

// ---------------- tf32 grouped GEMM -----------------------------------------
__device__ __forceinline__ uint32_t f2tf(float f) {
    uint32_t r;
    asm("cvt.rna.tf32.f32 %0, %1;" : "=r"(r) : "f"(f));
    return r;
}
__device__ __forceinline__ void cpa16(uint32_t s, const void* g) {
    asm volatile("cp.async.cg.shared.global [%0], [%1], 16;\n" ::"r"(s), "l"(g));
}

// smem layout (floats): As[2][128*36], Bs[2][32*136]
#define A_STRIDE 36
#define B_STRIDE 136
#define A_BUF (128 * A_STRIDE)       // 4608 floats
#define B_BUF (32 * B_STRIDE)        // 4352 floats
#define SMEM_BYTES ((2 * A_BUF + 2 * B_BUF) * 4)   // 71680 B

template <int KTOT, int NTOT, bool G2>
__global__ __launch_bounds__(256) void moe_gemm(
    const float* __restrict__ Abase,  // x for G1 (unused for G2)
    const float* __restrict__ Wt,     // W1 or W2 base [E][KTOT][NTOT]
    const float* __restrict__ bias,   // b1 [E][NTOT] or b2 [E][NTOT]
    float* __restrict__ outp)         // unused G1 (writes g_hidden) / d_out G2
{
    const int e = blockIdx.z;
    const int cnt = g_count[e];
    const int m_base = blockIdx.y * 128;
    if (m_base >= cnt) return;
    const int n_base = blockIdx.x * 128;
    const int tid = threadIdx.x;
    const int lane = tid & 31;
    const int warp = tid >> 5;
    const int wm = warp >> 2;   // 0..1
    const int wn = warp & 3;    // 0..3

    extern __shared__ float smem[];
    float* As = smem;
    float* Bs = smem + 2 * A_BUF;
    uint32_t As_u = (uint32_t)__cvta_generic_to_shared(As);
    uint32_t Bs_u = (uint32_t)__cvta_generic_to_shared(Bs);

    // ---- per-thread load assignment ----
    // A: 2 threads per row; each moves 16 floats (4 x 16B) per stage
    const int ar = tid >> 1;
    int am = m_base + ar; if (am > cnt - 1) am = cnt - 1;
    const float* a_g;
    if (G2) a_g = g_hidden + (size_t)(g_off[e] + am) * KTOT;
    else    a_g = Abase + (size_t)g_list[e][am] * KTOT;
    a_g += (tid & 1) * 16;
    const uint32_t a_dst = (uint32_t)((ar * A_STRIDE + (tid & 1) * 16) * 4);

    // B: 8 threads per k-row; each moves 16 floats per stage
    const int rb = tid >> 3;
    const float* b_g = Wt + (size_t)e * KTOT * NTOT + (size_t)rb * NTOT
                          + n_base + (tid & 7) * 16;
    const uint32_t b_dst = (uint32_t)((rb * B_STRIDE + (tid & 7) * 16) * 4);

    auto load_stage = [&](int s) {
        int buf = s & 1;
        const float* ag = a_g + s * 32;
        uint32_t ad = As_u + buf * (A_BUF * 4) + a_dst;
        cpa16(ad,      ag);
        cpa16(ad + 16, ag + 4);
        cpa16(ad + 32, ag + 8);
        cpa16(ad + 48, ag + 12);
        const float* bg = b_g + (size_t)s * 32 * NTOT;
        uint32_t bd = Bs_u + buf * (B_BUF * 4) + b_dst;
        cpa16(bd,      bg);
        cpa16(bd + 16, bg + 4);
        cpa16(bd + 32, bg + 8);
        cpa16(bd + 48, bg + 12);
        asm volatile("cp.async.commit_group;\n" ::);
    };

    float acc[16][4];
#pragma unroll
    for (int i = 0; i < 16; i++)
#pragma unroll
        for (int j = 0; j < 4; j++) acc[i][j] = 0.f;

    constexpr int NS = KTOT / 32;
    load_stage(0);

    for (int s = 0; s < NS; s++) {
        if (s + 1 < NS) {
            load_stage(s + 1);
            asm volatile("cp.async.wait_group 1;\n" ::);
        } else {
            asm volatile("cp.async.wait_group 0;\n" ::);
        }
        __syncthreads();

        const float* Ab = As + (s & 1) * A_BUF;
        const float* Bb = Bs + (s & 1) * B_BUF;
#pragma unroll
        for (int kk = 0; kk < 4; kk++) {
            const int kb = kk * 8 + (lane & 3);
            uint32_t af[4][4];
            uint32_t bf[4][2];
#pragma unroll
            for (int mi = 0; mi < 4; mi++) {
                int mr = wm * 64 + mi * 16 + (lane >> 2);
                af[mi][0] = f2tf(Ab[mr * A_STRIDE + kb]);
                af[mi][1] = f2tf(Ab[(mr + 8) * A_STRIDE + kb]);
                af[mi][2] = f2tf(Ab[mr * A_STRIDE + kb + 4]);
                af[mi][3] = f2tf(Ab[(mr + 8) * A_STRIDE + kb + 4]);
            }
#pragma unroll
            for (int ni = 0; ni < 4; ni++) {
                int nc = wn * 32 + ni * 8 + (lane >> 2);
                bf[ni][0] = f2tf(Bb[kb * B_STRIDE + nc]);
                bf[ni][1] = f2tf(Bb[(kb + 4) * B_STRIDE + nc]);
            }
#pragma unroll
            for (int mi = 0; mi < 4; mi++)
#pragma unroll
                for (int ni = 0; ni < 4; ni++) {
                    float* c = acc[mi * 4 + ni];
                    asm volatile(
                        "mma.sync.aligned.m16n8k8.row.col.f32.tf32.tf32.f32 "
                        "{%0,%1,%2,%3},{%4,%5,%6,%7},{%8,%9},{%0,%1,%2,%3};"
                        : "+f"(c[0]), "+f"(c[1]), "+f"(c[2]), "+f"(c[3])
                        : "r"(af[mi][0]), "r"(af[mi][1]), "r"(af[mi][2]), "r"(af[mi][3]),
                          "r"(bf[ni][0]), "r"(bf[ni][1]));
                }
        }
        __syncthreads();
    }

    // ---- epilogue ----
    const int off = g_off[e];
#pragma unroll
    for (int mi = 0; mi < 4; mi++) {
        int r0 = wm * 64 + mi * 16 + (lane >> 2);
        int r1 = r0 + 8;
        int t0 = 0, t1 = 0; float w0f = 0.f, w1f = 0.f;
        bool v0 = (m_base + r0 < cnt), v1 = (m_base + r1 < cnt);
        if (G2) {
            if (v0) { t0 = g_list[e][m_base + r0]; w0f = g_wlist[e][m_base + r0]; }
            if (v1) { t1 = g_list[e][m_base + r1]; w1f = g_wlist[e][m_base + r1]; }
        }
#pragma unroll
        for (int ni = 0; ni < 4; ni++) {
            int c = wn * 32 + ni * 8 + (lane & 3) * 2;
            int h = n_base + c;
            float bv0 = bias[(size_t)e * NTOT + h];
            float bv1 = bias[(size_t)e * NTOT + h + 1];
            float* a = acc[mi * 4 + ni];
            if (!G2) {
                if (v0) {
                    float2 v = make_float2(fmaxf(a[0] + bv0, 0.f),
                                           fmaxf(a[1] + bv1, 0.f));
                    *reinterpret_cast<float2*>(
                        &g_hidden[(size_t)(off + m_base + r0) * NTOT + h]) = v;
                }
                if (v1) {
                    float2 v = make_float2(fmaxf(a[2] + bv0, 0.f),
                                           fmaxf(a[3] + bv1, 0.f));
                    *reinterpret_cast<float2*>(
                        &g_hidden[(size_t)(off + m_base + r1) * NTOT + h]) = v;
                }
            } else {
                if (v0) {
                    atomicAdd(&outp[(size_t)t0 * NTOT + h],     w0f * (a[0] + bv0));
                    atomicAdd(&outp[(size_t)t0 * NTOT + h + 1], w0f * (a[1] + bv1));
                }
                if (v1) {
                    atomicAdd(&outp[(size_t)t1 * NTOT + h],     w1f * (a[2] + bv0));
                    atomicAdd(&outp[(size_t)t1 * NTOT + h + 1], w1f * (a[3] + bv1));
                }
            }
        }
    }
}

// ---------------- launch -----------------------------------------------------
extern "C" void kernel_launch(void* const* d_in, const int* in_sizes, int n_in,
                              void* d_out, int out_size) {
    const float* x  = (const float*)d_in[0];
    const float* gw = (const float*)d_in[1];
    const float* gb = (const float*)d_in[2];
    const float* W1 = (const float*)d_in[3];
    const float* b1 = (const float*)d_in[4];
    const float* W2 = (const float*)d_in[5];
    const float* b2 = (const float*)d_in[6];
    float* out = (float*)d_out;

    void* cnt_ptr = nullptr;
    cudaGetSymbolAddress(&cnt_ptr, g_count);
    cudaMemsetAsync(cnt_ptr, 0, sizeof(int) * NE);
    cudaMemsetAsync(d_out, 0, (size_t)out_size * sizeof(float));

    gate_kernel<<<TOK / 8, 256>>>(x, gw, gb);
    offs_kernel<<<1, 1>>>();

    cudaFuncSetAttribute((const void*)moe_gemm<DID, HID, false>,
                         cudaFuncAttributeMaxDynamicSharedMemorySize, SMEM_BYTES);
    cudaFuncSetAttribute((const void*)moe_gemm<HID, DID, true>,
                         cudaFuncAttributeMaxDynamicSharedMemorySize, SMEM_BYTES);

    // GEMM1: [cnt_e x 1024] @ W1[e] (1024x4096) -> relu -> hidden
    moe_gemm<DID, HID, false><<<dim3(HID / 128, TOK / 128, NE), 256, SMEM_BYTES>>>(
        x, W1, b1, nullptr);
    // GEMM2: hidden @ W2[e] (4096x1024) -> +b2 -> w * y scatter-add into out
    moe_gemm<HID, DID, true><<<dim3(DID / 128, TOK / 128, NE), 256, SMEM_BYTES>>>(
        nullptr, W2, b2, out);
}